// round 13
// baseline (speedup 1.0000x reference)
#include <cuda_runtime.h>
#include <math.h>
#include <stdint.h>

typedef unsigned long long ull;

#define BB 256
#define HH 512
#define TT 512

#define CS 8        // CTAs per cluster
#define ROWS 64     // H rows per CTA
#define BT 16       // batch elems per cluster
#define NTH 256

// Output layout (flattened tuple: keys, prs, hs, tm_modified), float32
#define KEYS_OFF 0
#define PRS_OFF  (BB * 2 * TT)
#define HS_OFF   (PRS_OFF + BB * 4 * TT)
#define TM_OFF   (HS_OFF + (size_t)BB * HH * TT)

// Shared layout (float offsets)
#define HST 18                              // ull stride per k in sHb2 (bank-spread)
#define OFF_WT   0                          // float [512][64]  W_rec^T slice (128 KB)
#define OFF_HB2  32768                      // ull   [512][HST] dup'd h (73728 B)
#define OFF_WIN  (OFF_HB2 + HH * HST * 2)   // float [6][64]
#define OFF_BIAS (OFF_WIN + 6 * ROWS)       // float [64]
#define OFF_WK   (OFF_BIAS + ROWS)          // float [2][512]
#define OFF_INPU (OFF_WK + 2 * HH)          // ull   [6][16]  (192 floats)
#define OFF_KEY  (OFF_INPU + 192)           // float [16]
#define OFF_BK   (OFF_KEY + 16)             // float [2] + pad
#define SMEM_FLOATS (OFF_BK + 4)
#define SMEM_BYTES  (SMEM_FLOATS * 4)       // ~211.6 KB

__device__ float g_scr[(size_t)TT * BB * HH];   // h in [t][b][i] (for exchange)
__device__ float g_key[BB];                     // key carry across launches

__device__ __forceinline__ ull pack2(float x, float y) {
    ull r; asm("mov.b64 %0, {%1, %2};" : "=l"(r) : "f"(x), "f"(y)); return r;
}
__device__ __forceinline__ void unpack2(float& x, float& y, ull v) {
    asm("mov.b64 {%0, %1}, %2;" : "=f"(x), "=f"(y) : "l"(v));
}
__device__ __forceinline__ void ffma2(ull& d, ull a, ull b) {
    asm("fma.rn.f32x2 %0, %1, %2, %0;" : "+l"(d) : "l"(a), "l"(b));
}
__device__ __forceinline__ float ftanh(float x) {
    float e = __expf(2.f * x);
    return 1.f - __fdividef(2.f, e + 1.f);
}

__global__ void __cluster_dims__(CS, 1, 1) __launch_bounds__(NTH, 1)
rnn_kernel(const float* __restrict__ xin,
           const float* __restrict__ Win,  const float* __restrict__ bin,
           const float* __restrict__ Wrec, const float* __restrict__ brec,
           const float* __restrict__ Wkey, const float* __restrict__ bkey,
           float* __restrict__ out, int t0, int nsteps)
{
    extern __shared__ float sm[];
    float* sWt   = sm + OFF_WT;
    ull*   sHb2  = (ull*)(sm + OFF_HB2);
    float* sWin  = sm + OFF_WIN;
    float* sBias = sm + OFF_BIAS;
    float* sWk   = sm + OFF_WK;
    ull*   sInpu = (ull*)(sm + OFF_INPU);
    float* sKey  = sm + OFF_KEY;
    float* sBk   = sm + OFF_BK;

    const int tid  = threadIdx.x;
    const int rank = blockIdx.x & (CS - 1);
    const int cid  = blockIdx.x / CS;
    const int b0   = cid * BT;
    const int row0 = rank * ROWS;

    // ---- init ----
    for (int idx = tid; idx < HH * ROWS; idx += NTH) {
        int r = idx & (ROWS - 1), k = idx >> 6;
        sWt[idx] = Wrec[(row0 + r) * HH + k];
    }
    for (int idx = tid; idx < 6 * ROWS; idx += NTH) {
        int r = idx & 63, j = idx >> 6;
        sWin[idx] = Win[(row0 + r) * 6 + j];
    }
    for (int idx = tid; idx < ROWS; idx += NTH)
        sBias[idx] = bin[row0 + idx] + brec[row0 + idx];
    for (int idx = tid; idx < 2 * HH; idx += NTH)
        sWk[idx] = Wkey[idx];
    if (tid < 2) sBk[tid] = bkey[tid];

    if (t0 == 1) {
        // h0 = zeros, key0 = ones
        for (int idx = tid; idx < HH * HST; idx += NTH)
            sHb2[idx] = 0ull;
        if (tid < BT) sKey[tid] = 1.f;
        // one-time output init (t=0 planes + tm copy), spread over 128 CTAs
        int gtid = blockIdx.x * NTH + tid;          // 0..32767
        {   // hs t=0 plane: 131072 zeros at stride TT
            int n0 = gtid * 4;
            float* p = out + HS_OFF;
            p[(size_t)(n0 + 0) * TT] = 0.f;
            p[(size_t)(n0 + 1) * TT] = 0.f;
            p[(size_t)(n0 + 2) * TT] = 0.f;
            p[(size_t)(n0 + 3) * TT] = 0.f;
        }
        if (gtid < BB * 2) out[KEYS_OFF + (size_t)gtid * TT] = 0.f;
        if (gtid < BB * 4) out[PRS_OFF + (size_t)gtid * TT] = 0.f;
        if (gtid < (BB * 2 * TT) / 16) {
            // tm_modified copy: 262144 floats, 16 per thread (float4 x4)
            int n0 = gtid * 16;
            int b = n0 >> 10, r = n0 & 1023;
            const float4* src = (const float4*)(xin + (size_t)b * 8 * TT + 6 * TT + r);
            float4* dst = (float4*)(out + TM_OFF + n0);
            dst[0] = src[0]; dst[1] = src[1]; dst[2] = src[2]; dst[3] = src[3];
        }
    } else {
        // load h_{t0-1} from previous launch into dup'd smem
        int rb = tid & 15, rc = tid >> 4;
        const float* src = g_scr + ((size_t)(t0 - 1) * BB + b0 + rb) * HH + rc * 32;
        #pragma unroll
        for (int q = 0; q < 8; q++) {
            float4 v = ((const float4*)src)[q];
            int k = rc * 32 + q * 4;
            sHb2[(k + 0) * HST + rb] = pack2(v.x, v.x);
            sHb2[(k + 1) * HST + rb] = pack2(v.y, v.y);
            sHb2[(k + 2) * HST + rb] = pack2(v.z, v.z);
            sHb2[(k + 3) * HST + rb] = pack2(v.w, v.w);
        }
        if (tid < BT) sKey[tid] = g_key[b0 + tid];
    }

    // GEMM decode: 2 rows x 2 batches per thread
    const int tb2 = (tid & 7) * 2;            // batches tb2, tb2+1
    const int r2  = ((tid >> 3) & 31) * 2;    // rows r2, r2+1
    const int bglob = b0 + tb2;

    // x prefetch: thread b (<16) holds its batch's 8 channels in regs
    float xv[8];
    const float* xrow = xin + (size_t)(b0 + (tid & 15)) * 8 * TT;
    if (tid < BT) {
        #pragma unroll
        for (int c = 0; c < 8; c++) xv[c] = xrow[c * TT + t0];
    }
    __syncthreads();

    for (int s = 0; s < nsteps; s++) {
        const int t = t0 + s;

        // ---- inp_t + prs (tid<16) while everyone else starts the GEMM ----
        if (tid < BT) {
            int b = tid;
            float kp = sKey[b];
            float a0 = xv[0], a1 = xv[1];
            float m0 = xv[2] * kp + xv[4] * (1.f - kp);
            float m1 = xv[3] * kp + xv[5] * (1.f - kp);
            float t0v = xv[6], t1v = xv[7];
            sInpu[0 * 16 + b] = pack2(a0, a0);
            sInpu[1 * 16 + b] = pack2(a1, a1);
            sInpu[2 * 16 + b] = pack2(m0, m0);
            sInpu[3 * 16 + b] = pack2(m1, m1);
            sInpu[4 * 16 + b] = pack2(t0v, t0v);
            sInpu[5 * 16 + b] = pack2(t1v, t1v);
            if (rank == 0) {
                float q0 = (t0v - a0) / (0.15f * a0); q0 *= q0; if (t0v == 0.f) q0 = 0.f;
                float q1 = (t0v - a1) / (0.15f * a1); q1 *= q1; if (t0v == 0.f) q1 = 0.f;
                float q2 = (t1v - m0) / (0.15f * m0); q2 *= q2; if (t1v == 0.f) q2 = 0.f;
                float q3 = (t1v - m1) / (0.15f * m1); q3 *= q3; if (t1v == 0.f) q3 = 0.f;
                float* p = out + PRS_OFF + (size_t)(b0 + b) * 4 * TT + t;
                p[0] = q0; p[TT] = q1; p[2 * TT] = q2; p[3 * TT] = q3;
            }
        }

        // ---- GEMM over h_{t-1}: 2 LDS + 2 fma.f32x2 per k ----
        ull bia = pack2(sBias[r2], sBias[r2 + 1]);
        ull A0 = bia, A1 = bia;               // {rows r2,r2+1} x {b, b+1}
        {
            const float* Wp = sWt + r2;
            const ull*   Hp = sHb2 + tb2;
            #pragma unroll 8
            for (int k = 0; k < HH; k++) {
                ull w = *(const ull*)(Wp + (k << 6));
                ulonglong2 hd = *(const ulonglong2*)(Hp + k * HST);
                ffma2(A0, w, hd.x);
                ffma2(A1, w, hd.y);
            }
        }
        __syncthreads();                      // B: sInpu ready

        // fold W_in, tanh, store h_t (exchange scratch + final hs layout)
        {
            #pragma unroll
            for (int j = 0; j < 6; j++) {
                ull w = *(const ull*)(sWin + j * 64 + r2);
                ulonglong2 xd = *(const ulonglong2*)(sInpu + j * 16 + tb2);
                ffma2(A0, w, xd.x);
                ffma2(A1, w, xd.y);
            }
            float h00, h01, h10, h11;
            unpack2(h00, h01, A0); unpack2(h10, h11, A1);
            h00 = ftanh(h00); h01 = ftanh(h01);
            h10 = ftanh(h10); h11 = ftanh(h11);
            size_t sbase = ((size_t)t * BB + bglob) * HH + row0 + r2;
            *(float2*)(g_scr + sbase)      = make_float2(h00, h01);
            *(float2*)(g_scr + sbase + HH) = make_float2(h10, h11);
            float* hp = out + HS_OFF + (size_t)bglob * HH * TT + (size_t)(row0 + r2) * TT + t;
            hp[0] = h00; hp[TT] = h01;
            hp += (size_t)HH * TT;
            hp[0] = h10; hp[TT] = h11;
        }

        // prefetch next x (latency hidden behind barrier+reload+keys)
        if (tid < BT && s + 1 < nsteps) {
            #pragma unroll
            for (int c = 0; c < 8; c++) xv[c] = xrow[c * TT + t + 1];
        }

        // ---- cluster-wide exchange of h_t (also a CTA-wide barrier) ----
        asm volatile("barrier.cluster.arrive.aligned;" ::: "memory");
        asm volatile("barrier.cluster.wait.aligned;"   ::: "memory");

        // reload full h_t (512 x 16) into dup'd smem
        {
            int rb = tid & 15, rc = tid >> 4;
            const float* src = g_scr + ((size_t)t * BB + b0 + rb) * HH + rc * 32;
            #pragma unroll
            for (int q = 0; q < 8; q++) {
                float4 v = ((const float4*)src)[q];
                int k = rc * 32 + q * 4;
                sHb2[(k + 0) * HST + rb] = pack2(v.x, v.x);
                sHb2[(k + 1) * HST + rb] = pack2(v.y, v.y);
                sHb2[(k + 2) * HST + rb] = pack2(v.z, v.z);
                sHb2[(k + 3) * HST + rb] = pack2(v.w, v.w);
            }
        }
        __syncthreads();                      // C: h_t visible in smem

        // ---- keys(t): 32 dots (16b x 2o), 8 lanes per dot ----
        {
            int l = tid & 7, g = tid >> 3;    // g 0..31
            int b = g >> 1, o = g & 1;
            const float* wk = sWk + o * HH;
            const float* hv = (const float*)sHb2;   // h at float idx k*(2*HST) + 2b
            const int b2 = b * 2;
            float p0 = 0.f, p1 = 0.f;
            #pragma unroll 8
            for (int m = 0; m < 64; m += 2) {
                int k0 = l + (m << 3);
                p0 = fmaf(wk[k0],     hv[(k0)     * (2 * HST) + b2], p0);
                p1 = fmaf(wk[k0 + 8], hv[(k0 + 8) * (2 * HST) + b2], p1);
            }
            float sum = p0 + p1;
            sum += __shfl_down_sync(0xffffffffu, sum, 4, 8);
            sum += __shfl_down_sync(0xffffffffu, sum, 2, 8);
            sum += __shfl_down_sync(0xffffffffu, sum, 1, 8);
            if (l == 0) {
                float kv = __fdividef(1.f, 1.f + __expf(-(sum + sBk[o])));
                if (o == 0) sKey[b] = kv;
                if (rank == 0) {
                    out[KEYS_OFF + (size_t)(b0 + b) * 2 * TT + o * TT + t] = kv;
                    if (o == 0) g_key[b0 + b] = kv;
                }
            }
        }
        __syncthreads();                      // A: sKey/sHb2 stable for next iter
    }
}

extern "C" void kernel_launch(void* const* d_in, const int* in_sizes, int n_in,
                              void* d_out, int out_size)
{
    const float* xin  = (const float*)d_in[0];
    const float* Win  = (const float*)d_in[1];
    const float* bin  = (const float*)d_in[2];
    const float* Wrec = (const float*)d_in[3];
    const float* brec = (const float*)d_in[4];
    const float* Wkey = (const float*)d_in[5];
    const float* bkey = (const float*)d_in[6];
    float* out = (float*)d_out;

    cudaFuncSetAttribute(rnn_kernel,
                         cudaFuncAttributeMaxDynamicSharedMemorySize, SMEM_BYTES);

    // only rnn launches -> ncu -s 5 -c 1 must land on rnn_kernel
    rnn_kernel<<<(BB / BT) * CS, NTH, SMEM_BYTES>>>(xin, Win, bin, Wrec, brec,
                                                    Wkey, bkey, out, 1, 255);
    rnn_kernel<<<(BB / BT) * CS, NTH, SMEM_BYTES>>>(xin, Win, bin, Wrec, brec,
                                                    Wkey, bkey, out, 256, 256);
}

// round 15
// speedup vs baseline: 1.3477x; 1.3477x over previous
#include <cuda_runtime.h>
#include <math.h>
#include <stdint.h>

typedef unsigned long long ull;

#define BB 256
#define HH 512
#define TT 512

#define CS 8        // CTAs per group (W_rec shard width)
#define ROWS 64     // H rows per CTA
#define BT 16       // batch elems per group
#define NTH 256

// Output layout (flattened tuple: keys, prs, hs, tm_modified), float32
#define KEYS_OFF 0
#define PRS_OFF  (BB * 2 * TT)
#define HS_OFF   (PRS_OFF + BB * 4 * TT)
#define TM_OFF   (HS_OFF + (size_t)BB * HH * TT)

// Shared layout (float offsets)
#define HST 18                              // ull stride per k in sHb2
#define OFF_WT   0                          // float [512][64] W_rec^T slice (128 KB)
#define OFF_HB2  32768                      // ull   [512][HST] dup'd h
#define OFF_WIN  (OFF_HB2 + HH * HST * 2)   // float [6][64]
#define OFF_BIAS (OFF_WIN + 6 * ROWS)       // float [64]
#define OFF_WK   (OFF_BIAS + ROWS)          // float [2][512]
#define OFF_INPU (OFF_WK + 2 * HH)          // ull   [6][16]
#define OFF_KEY  (OFF_INPU + 192)           // float [16]
#define OFF_BK   (OFF_KEY + 16)             // float [2] + pad
#define OFF_KP   (OFF_BK + 4)               // float [16][32] key partials
#define SMEM_FLOATS (OFF_KP + 512)
#define SMEM_BYTES  (SMEM_FLOATS * 4)       // ~213.6 KB

__device__ float g_scr[(size_t)TT * BB * HH];   // h in [t][b][i]
__device__ float g_key[BB];                     // key carry across launches
__device__ int   g_flag[16 * 32];               // per-group arrival counters (128B stride)

__device__ __forceinline__ ull pack2(float x, float y) {
    ull r; asm("mov.b64 %0, {%1, %2};" : "=l"(r) : "f"(x), "f"(y)); return r;
}
__device__ __forceinline__ void unpack2(float& x, float& y, ull v) {
    asm("mov.b64 {%0, %1}, %2;" : "=f"(x), "=f"(y) : "l"(v));
}
__device__ __forceinline__ void ffma2(ull& d, ull a, ull b) {
    asm("fma.rn.f32x2 %0, %1, %2, %0;" : "+l"(d) : "l"(a), "l"(b));
}
__device__ __forceinline__ float ftanh(float x) {
    float e = __expf(2.f * x);
    return 1.f - __fdividef(2.f, e + 1.f);
}

__global__ void __launch_bounds__(NTH, 1)
rnn_kernel(const float* __restrict__ xin,
           const float* __restrict__ Win,  const float* __restrict__ bin,
           const float* __restrict__ Wrec, const float* __restrict__ brec,
           const float* __restrict__ Wkey, const float* __restrict__ bkey,
           float* __restrict__ out, int t0, int nsteps)
{
    extern __shared__ float sm[];
    float* sWt   = sm + OFF_WT;
    ull*   sHb2  = (ull*)(sm + OFF_HB2);
    float* sWin  = sm + OFF_WIN;
    float* sBias = sm + OFF_BIAS;
    float* sWk   = sm + OFF_WK;
    ull*   sInpu = (ull*)(sm + OFF_INPU);
    float* sKey  = sm + OFF_KEY;
    float* sBk   = sm + OFF_BK;
    float* sKp   = sm + OFF_KP;

    const int tid   = threadIdx.x;
    const int grank = blockIdx.x & (CS - 1);
    const int gid   = blockIdx.x / CS;
    const int b0    = gid * BT;
    const int row0  = grank * ROWS;
    int* flagp = g_flag + gid * 32;

    // ---- init ----
    for (int idx = tid; idx < HH * ROWS; idx += NTH) {
        int r = idx & (ROWS - 1), k = idx >> 6;
        sWt[idx] = Wrec[(row0 + r) * HH + k];
    }
    for (int idx = tid; idx < 6 * ROWS; idx += NTH) {
        int r = idx & 63, j = idx >> 6;
        sWin[idx] = Win[(row0 + r) * 6 + j];
    }
    for (int idx = tid; idx < ROWS; idx += NTH)
        sBias[idx] = bin[row0 + idx] + brec[row0 + idx];
    for (int idx = tid; idx < 2 * HH; idx += NTH)
        sWk[idx] = Wkey[idx];
    if (tid < 2) sBk[tid] = bkey[tid];

    if (t0 == 1) {
        for (int idx = tid; idx < HH * HST; idx += NTH)
            sHb2[idx] = 0ull;                 // h0 = zeros (covers dup'd region)
        if (tid < BT) sKey[tid] = 1.f;        // key0 = ones
    } else {
        // load h_{t0-1} from previous launch
        int rb = tid & 15, rc = tid >> 4;
        const float* src = g_scr + ((size_t)(t0 - 1) * BB + b0 + rb) * HH + rc * 32;
        #pragma unroll
        for (int q = 0; q < 8; q++) {
            float4 v = ((const float4*)src)[q];
            int k = rc * 32 + q * 4;
            sHb2[(k + 0) * HST + rb] = pack2(v.x, v.x);
            sHb2[(k + 1) * HST + rb] = pack2(v.y, v.y);
            sHb2[(k + 2) * HST + rb] = pack2(v.z, v.z);
            sHb2[(k + 3) * HST + rb] = pack2(v.w, v.w);
        }
        if (tid < BT) sKey[tid] = g_key[b0 + tid];
    }

    // GEMM decode: 2 rows x 2 batches per thread
    const int tb2 = (tid & 7) * 2;
    const int r2  = ((tid >> 3) & 31) * 2;
    const int bglob = b0 + tb2;

    // x prefetch (tid<16 holds its batch's 8 channels)
    float xv[8];
    const float* xrow = xin + (size_t)(b0 + (tid & 15)) * 8 * TT;
    if (tid < BT) {
        #pragma unroll
        for (int c = 0; c < 8; c++) xv[c] = xrow[c * TT + t0];
    }
    __syncthreads();

    for (int s = 0; s < nsteps; s++) {
        const int t = t0 + s;

        // ---- inp_t + prs (tid<16), overlapped with GEMM start ----
        if (tid < BT) {
            int b = tid;
            float kp = sKey[b];
            float a0 = xv[0], a1 = xv[1];
            float m0 = xv[2] * kp + xv[4] * (1.f - kp);
            float m1 = xv[3] * kp + xv[5] * (1.f - kp);
            float t0v = xv[6], t1v = xv[7];
            sInpu[0 * 16 + b] = pack2(a0, a0);
            sInpu[1 * 16 + b] = pack2(a1, a1);
            sInpu[2 * 16 + b] = pack2(m0, m0);
            sInpu[3 * 16 + b] = pack2(m1, m1);
            sInpu[4 * 16 + b] = pack2(t0v, t0v);
            sInpu[5 * 16 + b] = pack2(t1v, t1v);
            if (grank == 0) {
                float q0 = (t0v - a0) / (0.15f * a0); q0 *= q0; if (t0v == 0.f) q0 = 0.f;
                float q1 = (t0v - a1) / (0.15f * a1); q1 *= q1; if (t0v == 0.f) q1 = 0.f;
                float q2 = (t1v - m0) / (0.15f * m0); q2 *= q2; if (t1v == 0.f) q2 = 0.f;
                float q3 = (t1v - m1) / (0.15f * m1); q3 *= q3; if (t1v == 0.f) q3 = 0.f;
                float* p = out + PRS_OFF + (size_t)(b0 + b) * 4 * TT + t;
                p[0] = q0; p[TT] = q1; p[2 * TT] = q2; p[3 * TT] = q3;
            }
        }

        // ---- GEMM over h_{t-1} ----
        ull bia = pack2(sBias[r2], sBias[r2 + 1]);
        ull A0 = bia, A1 = bia;
        {
            const float* Wp = sWt + r2;
            const ull*   Hp = sHb2 + tb2;
            #pragma unroll 8
            for (int k = 0; k < HH; k++) {
                ull w = *(const ull*)(Wp + (k << 6));
                ulonglong2 hd = *(const ulonglong2*)(Hp + k * HST);
                ffma2(A0, w, hd.x);
                ffma2(A1, w, hd.y);
            }
        }
        __syncthreads();                      // B: sInpu ready, GEMM reads done

        // fold W_in, tanh, coalesced h_t store to scratch
        {
            #pragma unroll
            for (int j = 0; j < 6; j++) {
                ull w = *(const ull*)(sWin + j * 64 + r2);
                ulonglong2 xd = *(const ulonglong2*)(sInpu + j * 16 + tb2);
                ffma2(A0, w, xd.x);
                ffma2(A1, w, xd.y);
            }
            float h00, h01, h10, h11;
            unpack2(h00, h01, A0); unpack2(h10, h11, A1);
            size_t sbase = ((size_t)t * BB + bglob) * HH + row0 + r2;
            *(float2*)(g_scr + sbase)      = make_float2(ftanh(h00), ftanh(h01));
            *(float2*)(g_scr + sbase + HH) = make_float2(ftanh(h10), ftanh(h11));
        }

        // prefetch next x
        if (tid < BT && s + 1 < nsteps) {
            #pragma unroll
            for (int c = 0; c < 8; c++) xv[c] = xrow[c * TT + t + 1];
        }
        __syncthreads();                      // C1: all h_t stores issued

        // ---- software group barrier: release our arrival, acquire peers' ----
        // Counter is cumulative across both launches (zeroed once per replay by
        // misc_kernel): after every CTA of the group has finished step t it
        // holds >= 8*t. Fast CTAs arriving for later steps only increase it.
        if (tid == 0) {
            asm volatile("red.release.gpu.global.add.s32 [%0], 1;"
                         :: "l"(flagp) : "memory");
            int target = 8 * t;
            int v;
            do {
                asm volatile("ld.acquire.gpu.global.s32 %0, [%1];"
                             : "=r"(v) : "l"(flagp) : "memory");
            } while (v < target);
        }
        __syncthreads();                      // C2: h_t globally visible

        // ---- reload h_t into dup'd smem + fused key partials ----
        {
            int rb = tid & 15, rc = tid >> 4;
            const float* src = g_scr + ((size_t)t * BB + b0 + rb) * HH + rc * 32;
            const float* wk0 = sWk + rc * 32;
            const float* wk1 = sWk + HH + rc * 32;
            float p0 = 0.f, p1 = 0.f;
            #pragma unroll
            for (int q = 0; q < 8; q++) {
                float4 v = ((const float4*)src)[q];
                int k = rc * 32 + q * 4;
                sHb2[(k + 0) * HST + rb] = pack2(v.x, v.x);
                sHb2[(k + 1) * HST + rb] = pack2(v.y, v.y);
                sHb2[(k + 2) * HST + rb] = pack2(v.z, v.z);
                sHb2[(k + 3) * HST + rb] = pack2(v.w, v.w);
                int q4 = q * 4;
                p0 = fmaf(wk0[q4],     v.x, p0); p0 = fmaf(wk0[q4 + 1], v.y, p0);
                p0 = fmaf(wk0[q4 + 2], v.z, p0); p0 = fmaf(wk0[q4 + 3], v.w, p0);
                p1 = fmaf(wk1[q4],     v.x, p1); p1 = fmaf(wk1[q4 + 1], v.y, p1);
                p1 = fmaf(wk1[q4 + 2], v.z, p1); p1 = fmaf(wk1[q4 + 3], v.w, p1);
            }
            sKp[rc * 32 + rb * 2 + 0] = p0;
            sKp[rc * 32 + rb * 2 + 1] = p1;
        }
        __syncthreads();                      // C3: sHb2 + partials ready

        // ---- keys(t): finish 32 dots from 16 partials each ----
        if (tid < 32) {
            int b = tid >> 1, o = tid & 1;
            float sum = sBk[o];
            #pragma unroll
            for (int rc = 0; rc < 16; rc++) sum += sKp[rc * 32 + tid];
            float kv = __fdividef(1.f, 1.f + __expf(-sum));
            if (o == 0) sKey[b] = kv;
            if (grank == 0) {
                out[KEYS_OFF + (size_t)(b0 + b) * 2 * TT + o * TT + t] = kv;
                if (o == 0 && s == nsteps - 1) g_key[b0 + b] = kv;
            }
        }
        __syncthreads();                      // A: sKey/sHb2 stable for next iter
    }
}

// Zero t=0 slab / carries / flags, zero keys+prs t=0 planes, copy tm_modified.
__global__ void misc_kernel(const float* __restrict__ xin, float* __restrict__ out)
{
    int idx = blockIdx.x * blockDim.x + threadIdx.x;
    if (idx < BB * HH) g_scr[idx] = 0.f;
    if (idx < BB)      g_key[idx] = 1.f;
    if (idx < 16 * 32) g_flag[idx] = 0;
    if (idx < BB * 2)  out[KEYS_OFF + (size_t)idx * TT] = 0.f;
    if (idx < BB * 4)  out[PRS_OFF + (size_t)idx * TT] = 0.f;
    if (idx < BB * 2 * TT) {
        int b = idx >> 10, rr = idx & 1023;
        out[TM_OFF + idx] = xin[(size_t)b * 8 * TT + 6 * TT + rr];
    }
}

// Transpose scratch [t][b][i] -> hs (b, i, t), 32x32 tiles (covers t=0 zeros).
__global__ void transpose_kernel(float* __restrict__ out)
{
    __shared__ float tile[32][33];
    int b  = blockIdx.z;
    int i0 = blockIdx.y * 32;
    int t0 = blockIdx.x * 32;
    int tx = threadIdx.x, ty = threadIdx.y;
    #pragma unroll
    for (int j = 0; j < 32; j += 8)
        tile[ty + j][tx] =
            g_scr[(size_t)(t0 + ty + j) * BB * HH + (size_t)b * HH + i0 + tx];
    __syncthreads();
    float* dst = out + HS_OFF + (size_t)b * HH * TT;
    #pragma unroll
    for (int j = 0; j < 32; j += 8)
        dst[(size_t)(i0 + ty + j) * TT + t0 + tx] = tile[tx][ty + j];
}

extern "C" void kernel_launch(void* const* d_in, const int* in_sizes, int n_in,
                              void* d_out, int out_size)
{
    const float* xin  = (const float*)d_in[0];
    const float* Win  = (const float*)d_in[1];
    const float* bin  = (const float*)d_in[2];
    const float* Wrec = (const float*)d_in[3];
    const float* brec = (const float*)d_in[4];
    const float* Wkey = (const float*)d_in[5];
    const float* bkey = (const float*)d_in[6];
    float* out = (float*)d_out;

    cudaFuncSetAttribute(rnn_kernel,
                         cudaFuncAttributeMaxDynamicSharedMemorySize, SMEM_BYTES);

    misc_kernel<<<1024, 256>>>(xin, out);
    rnn_kernel<<<(BB / BT) * CS, NTH, SMEM_BYTES>>>(xin, Win, bin, Wrec, brec,
                                                    Wkey, bkey, out, 1, 255);
    rnn_kernel<<<(BB / BT) * CS, NTH, SMEM_BYTES>>>(xin, Win, bin, Wrec, brec,
                                                    Wkey, bkey, out, 256, 256);
    dim3 g(TT / 32, HH / 32, BB), blk(32, 8);
    transpose_kernel<<<g, blk>>>(out);
}